// round 6
// baseline (speedup 1.0000x reference)
#include <cuda_runtime.h>
#include <cuda_bf16.h>
#include <cstdint>
#include <cstddef>

constexpr int Kn = 1024, Cc = 128, Dd = 6272, FFNn = 1024, CPG = 32, DYN = 36864, Mb = 64;

// ---------------- fp32 scratch ----------------
__device__ __align__(128) float g_v   [(size_t)Kn * Dd];
__device__ __align__(128) float g_bufA[(size_t)Kn * Dd];
__device__ __align__(128) float g_x   [(size_t)Kn * Dd];
__device__ __align__(128) float g_flat[(size_t)Kn * Dd];
__device__ __align__(128) float g_gap [(size_t)Kn * Cc];
__device__ __align__(128) float g_dyn [(size_t)Kn * DYN];
__device__ __align__(128) float g_h   [(size_t)Kn * FFNn];
// ---------------- packed tf32 operands (MMA fragment order) ----------------
__device__ __align__(128) float pA_rf  [(size_t)Kn * Dd];
__device__ __align__(128) float pA_v   [(size_t)Kn * Dd];
__device__ __align__(128) float pA_gap [(size_t)Kn * Cc];
__device__ __align__(128) float pA_flat[(size_t)Kn * Dd];
__device__ __align__(128) float pA_h   [(size_t)Kn * FFNn];
__device__ __align__(128) float pB_wv  [(size_t)Dd * Dd];
__device__ __align__(128) float pB_wo  [(size_t)Dd * Dd];
__device__ __align__(128) float pB_wgn [(size_t)DYN * Cc];
__device__ __align__(128) float pB_wf1 [(size_t)FFNn * Dd];
__device__ __align__(128) float pB_wf2 [(size_t)Dd * FFNn];

// ---------------- PTX helpers ----------------
__device__ __forceinline__ uint32_t f2tf(float x) {
    uint32_t r;
    asm("cvt.rna.tf32.f32 %0, %1;" : "=r"(r) : "f"(x));
    return r;
}
__device__ __forceinline__ void mma_tf32(float* c, const uint32_t* a, const uint32_t* b) {
    asm volatile(
        "mma.sync.aligned.m16n8k8.row.col.f32.tf32.tf32.f32 "
        "{%0,%1,%2,%3}, {%4,%5,%6,%7}, {%8,%9}, {%0,%1,%2,%3};"
        : "+f"(c[0]), "+f"(c[1]), "+f"(c[2]), "+f"(c[3])
        : "r"(a[0]), "r"(a[1]), "r"(a[2]), "r"(a[3]), "r"(b[0]), "r"(b[1]));
}
#define CP_A16(dst, src) \
    asm volatile("cp.async.ca.shared.global [%0], [%1], 16;" :: "r"(dst), "l"(src) : "memory")
#define CP_COMMIT() asm volatile("cp.async.commit_group;" ::: "memory")
#define CP_WAIT2()  asm volatile("cp.async.wait_group 2;" ::: "memory")

// ============================================================
// Pack A: fp32 row-major [M,K] -> tf32 frags of 16m x 8k.
// Frag linear order: ((slab*KC + chunk)*(BM/16) + mf)*2 + kk.
// Lane L holds float4 {(r,k),(r+8,k),(r,k+4),(r+8,k+4)}, r=L>>2, k=L&3.
// ============================================================
__global__ void __launch_bounds__(256) pack_a(
    const float* __restrict__ src, float* __restrict__ dst, int K, int BM)
{
    const int f = blockIdx.x * 8 + (threadIdx.x >> 5);
    const int lane = threadIdx.x & 31;
    const int MF = BM / 16, KC = K / 16;
    const int kk = f & 1;
    int t = f >> 1;
    const int mf = t % MF; t /= MF;
    const int chunk = t % KC;
    const int slab = t / KC;
    const int m = slab * BM + mf * 16 + (lane >> 2);
    const int k = chunk * 16 + kk * 8 + (lane & 3);
    const float* s = src + (size_t)m * K + k;
    uint4 v;
    v.x = f2tf(s[0]);
    v.y = f2tf(s[(size_t)8 * K]);
    v.z = f2tf(s[4]);
    v.w = f2tf(s[(size_t)8 * K + 4]);
    *(uint4*)(dst + (size_t)f * 128 + lane * 4) = v;
}

// ============================================================
// Pack B: fp32 row-major [N,K] -> tf32 frags of 8n x 8k (BN slab = 128).
// Frag linear order: ((nslab*KC + chunk)*16 + nf)*2 + kk.
// Lane L holds float2 {(n,k),(n,k+4)}, n=L>>2, k=L&3.
// ============================================================
__global__ void __launch_bounds__(256) pack_b(
    const float* __restrict__ src, float* __restrict__ dst, int K)
{
    const int f = blockIdx.x * 8 + (threadIdx.x >> 5);
    const int lane = threadIdx.x & 31;
    const int KC = K / 16;
    const int kk = f & 1;
    int t = f >> 1;
    const int nf = t % 16; t /= 16;
    const int chunk = t % KC;
    const int nslab = t / KC;
    const int n = nslab * 128 + nf * 8 + (lane >> 2);
    const int k = chunk * 16 + kk * 8 + (lane & 3);
    const float* s = src + (size_t)n * K + k;
    uint2 v;
    v.x = f2tf(s[0]);
    v.y = f2tf(s[4]);
    *(uint2*)(dst + (size_t)f * 64 + lane * 2) = v;
}

// ============================================================
// Packed tf32 GEMM: C[M,N] = A·B^T + bias (+Res) (ReLU)
// Block tile (64*MW) x (64*NW), warp tile 64x64, k-tile 16,
// 4-stage cp.async pipeline, zero in-loop CVT, frag-ordered LDS.
// ============================================================
template<int MW, int NW, bool RELU, bool ADDRES>
__global__ void __launch_bounds__(MW * NW * 32, (MW * NW == 4) ? 2 : 1)
gemm_p(const float* __restrict__ pA, const float* __restrict__ pB,
       const float* __restrict__ bias, const float* __restrict__ Res,
       float* __restrict__ C, int N, int KC)
{
    constexpr int BM = 64 * MW, BN = 64 * NW;   // BN == 128 in all configs used
    constexpr int THREADS = MW * NW * 32;
    constexpr int AB = BM * 64, BB = BN * 64;   // bytes per stage plane
    constexpr int SB = AB + BB;                 // stage bytes
    constexpr int CA = AB / 16 / THREADS, CB = BB / 16 / THREADS;
    extern __shared__ char smc[];
    const uint32_t sbase = (uint32_t)__cvta_generic_to_shared(smc);

    const int tid = threadIdx.x, wid = tid >> 5, lane = tid & 31;
    const int lr = lane >> 2, lc = lane & 3;
    const int wm = wid % MW, wn = wid / MW;
    const int m0 = blockIdx.x * BM, n0 = blockIdx.y * BN;

    const char* Ab = (const char*)pA + (size_t)blockIdx.x * KC * AB;
    const char* Bb = (const char*)pB + (size_t)blockIdx.y * KC * BB;

    auto load = [&](int s, int c) {
        const uint32_t st = sbase + s * SB;
        const char* as = Ab + (size_t)c * AB;
        const char* bs = Bb + (size_t)c * BB;
        #pragma unroll
        for (int i = 0; i < CA; i++)
            CP_A16(st + (tid + i * THREADS) * 16, as + (size_t)(tid + i * THREADS) * 16);
        #pragma unroll
        for (int i = 0; i < CB; i++)
            CP_A16(st + AB + (tid + i * THREADS) * 16, bs + (size_t)(tid + i * THREADS) * 16);
    };

    float acc[4][8][4];
    #pragma unroll
    for (int mt = 0; mt < 4; mt++)
        #pragma unroll
        for (int nt = 0; nt < 8; nt++)
            #pragma unroll
            for (int q = 0; q < 4; q++) acc[mt][nt][q] = 0.f;

    #pragma unroll
    for (int s = 0; s < 3; s++) {
        if (s < KC) load(s, s);
        CP_COMMIT();
    }

    for (int kt = 0; kt < KC; ++kt) {
        CP_WAIT2();
        __syncthreads();
        if (kt + 3 < KC) load((kt + 3) & 3, kt + 3);
        CP_COMMIT();

        const char* st = smc + (kt & 3) * SB;
        #pragma unroll
        for (int kk = 0; kk < 2; kk++) {
            uint4 a[4];
            uint2 b[8];
            #pragma unroll
            for (int mt = 0; mt < 4; mt++)
                a[mt] = *(const uint4*)(st + ((wm * 4 + mt) * 2 + kk) * 512 + lane * 16);
            #pragma unroll
            for (int nt = 0; nt < 8; nt++)
                b[nt] = *(const uint2*)(st + AB + ((wn * 8 + nt) * 2 + kk) * 256 + lane * 8);
            #pragma unroll
            for (int mt = 0; mt < 4; mt++)
                #pragma unroll
                for (int nt = 0; nt < 8; nt++)
                    mma_tf32(acc[mt][nt], (const uint32_t*)&a[mt], (const uint32_t*)&b[nt]);
        }
    }

    // epilogue
    #pragma unroll
    for (int mt = 0; mt < 4; mt++) {
        #pragma unroll
        for (int nt = 0; nt < 8; nt++) {
            const int row0 = m0 + wm * 64 + mt * 16 + lr;
            const int col  = n0 + wn * 64 + nt * 8 + 2 * lc;
            const float b0 = bias[col], b1 = bias[col + 1];
            float v0 = acc[mt][nt][0] + b0, v1 = acc[mt][nt][1] + b1;
            float v2 = acc[mt][nt][2] + b0, v3 = acc[mt][nt][3] + b1;
            if (ADDRES) {
                float2 r0 = *(const float2*)(Res + (size_t)row0 * N + col);
                float2 r1 = *(const float2*)(Res + (size_t)(row0 + 8) * N + col);
                v0 += r0.x; v1 += r0.y; v2 += r1.x; v3 += r1.y;
            }
            if (RELU) {
                v0 = fmaxf(v0, 0.f); v1 = fmaxf(v1, 0.f);
                v2 = fmaxf(v2, 0.f); v3 = fmaxf(v3, 0.f);
            }
            *(float2*)(C + (size_t)row0 * N + col)       = make_float2(v0, v1);
            *(float2*)(C + (size_t)(row0 + 8) * N + col) = make_float2(v2, v3);
        }
    }
}

// ============================================================
// LayerNorm over Dd per row
// ============================================================
__global__ void __launch_bounds__(256) ln_kernel(
    const float* __restrict__ in, const float* __restrict__ g,
    const float* __restrict__ b, float* __restrict__ out)
{
    const int row = blockIdx.x, t = threadIdx.x;
    const float4* p = (const float4*)(in + (size_t)row * Dd);
    float s = 0.f, s2 = 0.f;
    for (int i = t; i < Dd / 4; i += 256) {
        float4 v = p[i];
        s += v.x + v.y + v.z + v.w;
        s2 += v.x * v.x + v.y * v.y + v.z * v.z + v.w * v.w;
    }
    #pragma unroll
    for (int o = 16; o > 0; o >>= 1) {
        s  += __shfl_xor_sync(~0u, s, o);
        s2 += __shfl_xor_sync(~0u, s2, o);
    }
    __shared__ float rs[8], rs2[8], smean, sinv;
    if ((t & 31) == 0) { rs[t >> 5] = s; rs2[t >> 5] = s2; }
    __syncthreads();
    if (t == 0) {
        float ts = 0.f, ts2 = 0.f;
        #pragma unroll
        for (int i = 0; i < 8; i++) { ts += rs[i]; ts2 += rs2[i]; }
        float mean = ts * (1.f / Dd);
        smean = mean;
        sinv = rsqrtf(ts2 * (1.f / Dd) - mean * mean + 1e-5f);
    }
    __syncthreads();
    const float mean = smean, inv = sinv;
    const float4 *g4 = (const float4*)g, *b4 = (const float4*)b;
    float4* o4 = (float4*)(out + (size_t)row * Dd);
    for (int i = t; i < Dd / 4; i += 256) {
        float4 v = p[i], gg = g4[i], bb = b4[i], r;
        r.x = (v.x - mean) * inv * gg.x + bb.x;
        r.y = (v.y - mean) * inv * gg.y + bb.y;
        r.z = (v.z - mean) * inv * gg.z + bb.z;
        r.w = (v.w - mean) * inv * gg.w + bb.w;
        o4[i] = r;
    }
}

__global__ void __launch_bounds__(128) gap_kernel(
    const float* __restrict__ x, float* __restrict__ gap)
{
    const float* p = x + ((size_t)blockIdx.x * Cc + threadIdx.x) * 49;
    float a = 0.f;
    #pragma unroll
    for (int i = 0; i < 49; i++) a += p[i];
    gap[(size_t)blockIdx.x * Cc + threadIdx.x] = a * (1.f / 49.f);
}

// ============================================================
// Per-sample grouped dynamic 3x3 conv + residual
// ============================================================
__global__ void __launch_bounds__(128) dynconv_kernel(
    const float* __restrict__ x, const float* __restrict__ dyn,
    float* __restrict__ out)
{
    const int s = blockIdx.x, t = threadIdx.x;
    __shared__ float sIn[Cc][81];
    float* sc = sIn[t];
    #pragma unroll
    for (int i = 0; i < 81; i++) sc[i] = 0.f;
    const float* xp = x + ((size_t)s * Cc + t) * 49;
    #pragma unroll
    for (int y = 0; y < 7; y++)
        #pragma unroll
        for (int xx = 0; xx < 7; xx++)
            sc[(y + 1) * 9 + xx + 1] = xp[y * 7 + xx];
    __syncthreads();

    const int grp = t >> 5;
    const float* wb = dyn + (size_t)s * DYN + (size_t)t * (CPG * 9);
    const float* ib = &sIn[grp * CPG][0];
    float acc[49];
    #pragma unroll
    for (int i = 0; i < 49; i++) acc[i] = 0.f;
    for (int ic = 0; ic < CPG; ic++) {
        const float* w = wb + ic * 9;
        const float* in = ib + ic * 81;
        float w0 = w[0], w1 = w[1], w2 = w[2], w3 = w[3], w4 = w[4];
        float w5 = w[5], w6 = w[6], w7 = w[7], w8 = w[8];
        #pragma unroll
        for (int y = 0; y < 7; y++) {
            #pragma unroll
            for (int xx = 0; xx < 7; xx++) {
                float a = acc[y * 7 + xx];
                a += w0 * in[y * 9 + xx]       + w1 * in[y * 9 + xx + 1]       + w2 * in[y * 9 + xx + 2];
                a += w3 * in[(y + 1) * 9 + xx] + w4 * in[(y + 1) * 9 + xx + 1] + w5 * in[(y + 1) * 9 + xx + 2];
                a += w6 * in[(y + 2) * 9 + xx] + w7 * in[(y + 2) * 9 + xx + 1] + w8 * in[(y + 2) * 9 + xx + 2];
                acc[y * 7 + xx] = a;
            }
        }
    }
    float* op = out + ((size_t)s * Cc + t) * 49;
    const float* ms = sIn[t];
    #pragma unroll
    for (int y = 0; y < 7; y++)
        #pragma unroll
        for (int xx = 0; xx < 7; xx++)
            op[y * 7 + xx] = acc[y * 7 + xx] + ms[(y + 1) * 9 + xx + 1];
}

// ============================================================
// cost matrix
// ============================================================
__global__ void __launch_bounds__(256) cost_kernel(
    const float* __restrict__ rb, const float* __restrict__ cb, float* __restrict__ out)
{
    __shared__ float sR[Mb * 4], sC[Mb * 4], sdist[Mb * Mb], rm[8], sMax;
    const int t = threadIdx.x;
    sR[t] = rb[t]; sC[t] = cb[t];
    __syncthreads();
    float lm = 0.f;
    for (int idx = t; idx < Mb * Mb; idx += 256) {
        int i = idx >> 6, j = idx & 63;
        float d = fabsf((sR[i * 4] + sR[i * 4 + 2]) * 0.5f - (sC[j * 4] + sC[j * 4 + 2]) * 0.5f)
                + fabsf((sR[i * 4 + 1] + sR[i * 4 + 3]) * 0.5f - (sC[j * 4 + 1] + sC[j * 4 + 3]) * 0.5f);
        sdist[idx] = d;
        lm = fmaxf(lm, d);
    }
    #pragma unroll
    for (int o = 16; o > 0; o >>= 1) lm = fmaxf(lm, __shfl_xor_sync(~0u, lm, o));
    if ((t & 31) == 0) rm[t >> 5] = lm;
    __syncthreads();
    if (t == 0) {
        float m = 0.f;
        #pragma unroll
        for (int i = 0; i < 8; i++) m = fmaxf(m, rm[i]);
        sMax = fmaxf(m, 1.f);
    }
    __syncthreads();
    const float dmax = sMax;
    for (int idx = t; idx < Mb * Mb; idx += 256) {
        int i = idx >> 6, j = idx & 63;
        float ax0 = sR[i*4], ay0 = sR[i*4+1], ax1 = sR[i*4+2], ay1 = sR[i*4+3];
        float bx0 = sC[j*4], by0 = sC[j*4+1], bx1 = sC[j*4+2], by1 = sC[j*4+3];
        float areaA = (ax1 - ax0) * (ay1 - ay0), areaB = (bx1 - bx0) * (by1 - by0);
        float w = fmaxf(fminf(ax1, bx1) - fmaxf(ax0, bx0), 0.f);
        float h = fmaxf(fminf(ay1, by1) - fmaxf(ay0, by0), 0.f);
        float inter = w * h;
        out[idx] = -inter / (areaA + areaB - inter) + 0.5f * sdist[idx] / dmax;
    }
}

// ============================================================
// host launcher
// ============================================================
extern "C" void kernel_launch(void* const* d_in, const int* in_sizes, int n_in,
                              void* d_out, int out_size)
{
    const float* wf     = (const float*)d_in[0];
    const float* rf     = (const float*)d_in[1];
    const float* refb   = (const float*)d_in[2];
    const float* curb   = (const float*)d_in[3];
    // d_in[4..7] = wq,bq,wk,bk: dead (softmax over one key == 1 -> attn == v)
    const float* wv     = (const float*)d_in[8];
    const float* bv     = (const float*)d_in[9];
    const float* wo     = (const float*)d_in[10];
    const float* bo     = (const float*)d_in[11];
    const float* g1     = (const float*)d_in[12];
    const float* b1     = (const float*)d_in[13];
    const float* wgen_w = (const float*)d_in[14];
    const float* wgen_b = (const float*)d_in[15];
    const float* g2     = (const float*)d_in[16];
    const float* b2     = (const float*)d_in[17];
    const float* wf1    = (const float*)d_in[18];
    const float* bf1    = (const float*)d_in[19];
    const float* wf2    = (const float*)d_in[20];
    const float* bf2    = (const float*)d_in[21];
    const float* g3     = (const float*)d_in[22];
    const float* b3     = (const float*)d_in[23];
    float* out = (float*)d_out;

    float *v, *bufA, *x, *flat, *gap, *dyn, *h;
    float *aRf, *aV, *aGap, *aFlat, *aH, *bWv, *bWo, *bWgn, *bWf1, *bWf2;
    cudaGetSymbolAddress((void**)&v, g_v);       cudaGetSymbolAddress((void**)&bufA, g_bufA);
    cudaGetSymbolAddress((void**)&x, g_x);       cudaGetSymbolAddress((void**)&flat, g_flat);
    cudaGetSymbolAddress((void**)&gap, g_gap);   cudaGetSymbolAddress((void**)&dyn, g_dyn);
    cudaGetSymbolAddress((void**)&h, g_h);
    cudaGetSymbolAddress((void**)&aRf, pA_rf);   cudaGetSymbolAddress((void**)&aV, pA_v);
    cudaGetSymbolAddress((void**)&aGap, pA_gap); cudaGetSymbolAddress((void**)&aFlat, pA_flat);
    cudaGetSymbolAddress((void**)&aH, pA_h);
    cudaGetSymbolAddress((void**)&bWv, pB_wv);   cudaGetSymbolAddress((void**)&bWo, pB_wo);
    cudaGetSymbolAddress((void**)&bWgn, pB_wgn); cudaGetSymbolAddress((void**)&bWf1, pB_wf1);
    cudaGetSymbolAddress((void**)&bWf2, pB_wf2);

    constexpr int SM42 = (256 + 128) * 64 * 4;   // 98304 B
    constexpr int SM22 = (128 + 128) * 64 * 4;   // 65536 B
    cudaFuncSetAttribute(gemm_p<4, 2, false, false>, cudaFuncAttributeMaxDynamicSharedMemorySize, SM42);
    cudaFuncSetAttribute(gemm_p<4, 2, false, true>,  cudaFuncAttributeMaxDynamicSharedMemorySize, SM42);
    cudaFuncSetAttribute(gemm_p<2, 2, true, false>,  cudaFuncAttributeMaxDynamicSharedMemorySize, SM22);

    auto fragsA = [](int M, int K) { return (M / 16) * (K / 8) / 8; };
    auto fragsB = [](int N, int K) { return (N / 8) * (K / 8) / 8; };

    // weight + input packs
    pack_a<<<fragsA(Kn, Dd), 256>>>(rf, aRf, Dd, 256);
    pack_b<<<fragsB(Dd, Dd), 256>>>(wv, bWv, Dd);
    pack_b<<<fragsB(Dd, Dd), 256>>>(wo, bWo, Dd);
    pack_b<<<fragsB(DYN, Cc), 256>>>(wgen_w, bWgn, Cc);
    pack_b<<<fragsB(FFNn, Dd), 256>>>(wf1, bWf1, Dd);
    pack_b<<<fragsB(Dd, FFNn), 256>>>(wf2, bWf2, FFNn);

    // 1. v = rf @ wv^T + bv
    gemm_p<4, 2, false, false><<<dim3(4, 49), 256, SM42>>>(aRf, bWv, bv, nullptr, v, Dd, Dd / 16);
    pack_a<<<fragsA(Kn, Dd), 256>>>(v, aV, Dd, 256);
    // 2. bufA = v @ wo^T + bo + wf
    gemm_p<4, 2, false, true><<<dim3(4, 49), 256, SM42>>>(aV, bWo, bo, wf, bufA, Dd, Dd / 16);
    // 3. x = LN(bufA)
    ln_kernel<<<Kn, 256>>>(bufA, g1, b1, x);
    // 4. gap
    gap_kernel<<<Kn, 128>>>(x, gap);
    pack_a<<<fragsA(Kn, Cc), 256>>>(gap, aGap, Cc, 256);
    // 5. dyn = gap @ wgen^T + wgen_b
    gemm_p<4, 2, false, false><<<dim3(4, 288), 256, SM42>>>(aGap, bWgn, wgen_b, nullptr, dyn, DYN, Cc / 16);
    // 6. bufA = dynconv(x) + x
    dynconv_kernel<<<Kn, 128>>>(x, dyn, bufA);
    // 7. flat = LN(bufA)
    ln_kernel<<<Kn, 256>>>(bufA, g2, b2, flat);
    pack_a<<<fragsA(Kn, Dd), 256>>>(flat, aFlat, Dd, 128);
    // 8. h = relu(flat @ wf1^T + bf1)
    gemm_p<2, 2, true, false><<<dim3(8, 8), 128, SM22>>>(aFlat, bWf1, bf1, nullptr, h, FFNn, Dd / 16);
    pack_a<<<fragsA(Kn, FFNn), 256>>>(h, aH, FFNn, 256);
    // 9. bufA = h @ wf2^T + bf2 + flat
    gemm_p<4, 2, false, true><<<dim3(4, 49), 256, SM42>>>(aH, bWf2, bf2, flat, bufA, Dd, FFNn / 16);
    // 10. out = LN(bufA)
    ln_kernel<<<Kn, 256>>>(bufA, g3, b3, out);
    // 11. cost matrix
    cost_kernel<<<1, 256>>>(refb, curb, out + (size_t)Kn * Dd);
}

// round 7
// speedup vs baseline: 1.0311x; 1.0311x over previous
#include <cuda_runtime.h>
#include <cuda_bf16.h>
#include <cstdint>
#include <cstddef>

constexpr int Kn = 1024, Cc = 128, Dd = 6272, FFNn = 1024, CPG = 32, DYN = 36864, Mb = 64;

// ---------------- fp32 scratch ----------------
__device__ __align__(128) float g_v   [(size_t)Kn * Dd];
__device__ __align__(128) float g_bufA[(size_t)Kn * Dd];
__device__ __align__(128) float g_x   [(size_t)Kn * Dd];
__device__ __align__(128) float g_flat[(size_t)Kn * Dd];
__device__ __align__(128) float g_gap [(size_t)Kn * Cc];
__device__ __align__(128) float g_dyn [(size_t)Kn * DYN];
__device__ __align__(128) float g_h   [(size_t)Kn * FFNn];
__device__ __align__(128) float g_part[(size_t)2 * Kn * Dd];   // split-K partials

// ---------------- PTX helpers ----------------
__device__ __forceinline__ float f2tf(float x) {
    uint32_t r;
    asm("cvt.rna.tf32.f32 %0, %1;" : "=r"(r) : "f"(x));
    return __uint_as_float(r);
}
__device__ __forceinline__ void mma_tf32(float* c, const uint32_t* a, const uint32_t* b) {
    asm volatile(
        "mma.sync.aligned.m16n8k8.row.col.f32.tf32.tf32.f32 "
        "{%0,%1,%2,%3}, {%4,%5,%6,%7}, {%8,%9}, {%0,%1,%2,%3};"
        : "+f"(c[0]), "+f"(c[1]), "+f"(c[2]), "+f"(c[3])
        : "r"(a[0]), "r"(a[1]), "r"(a[2]), "r"(a[3]), "r"(b[0]), "r"(b[1]));
}

// ============================================================
// Fused-convert tf32 GEMM: C[M,N] = A[M,K]·B[N,K]^T (+bias/res/relu if Z==1)
// Block 256x128, 8 warps (64x64 each), k-tile 16.
// Loader: LDG.128 -> cvt.rna.tf32 -> STS.128, 2-stage double buffer.
// gridDim.z = Z-way split-K; Z>1 writes raw partials to `part`.
// ============================================================
constexpr int SROW = 20;                 // padded floats per 16-float k row
constexpr int AF = 256 * SROW;           // A stage floats
constexpr int BF = 128 * SROW;           // B stage floats
constexpr int STAGE_F = AF + BF;         // 7680 floats
constexpr int GEMM_SMEM = 2 * STAGE_F * 4;  // 61440 bytes

template<bool RELU, bool ADDRES>
__global__ void __launch_bounds__(256, 1) gemm_f(
    const float* __restrict__ A, const float* __restrict__ B,
    const float* __restrict__ bias, const float* __restrict__ Res,
    float* __restrict__ C, float* __restrict__ part,
    int N, int Kd, int KC)
{
    extern __shared__ float sm[];
    const int tid = threadIdx.x;
    const int wid = tid >> 5, lane = tid & 31;
    const int lr = lane >> 2, lc = lane & 3;
    const int wm = wid & 3, wn = wid >> 2;      // 4 m-warps x 2 n-warps
    const int m0 = blockIdx.x * 256, n0 = blockIdx.y * 128;
    const int Z = gridDim.z, KCz = KC / Z, kc0 = blockIdx.z * KCz;
    const int M = gridDim.x * 256;

    const int ldr = tid >> 2, ldq = tid & 3;    // row within 4x256-chunk, float4 col

    float4 ra[4], rb[2];
    auto ldg = [&](int c) {
        const int ko = (kc0 + c) * 16 + ldq * 4;
        #pragma unroll
        for (int i = 0; i < 4; i++)
            ra[i] = *(const float4*)(A + (size_t)(m0 + ldr + i * 64) * Kd + ko);
        #pragma unroll
        for (int i = 0; i < 2; i++)
            rb[i] = *(const float4*)(B + (size_t)(n0 + ldr + i * 64) * Kd + ko);
    };
    auto sts = [&](int s) {
        float* d = sm + s * STAGE_F;
        #pragma unroll
        for (int i = 0; i < 4; i++)
            *(float4*)(d + (ldr + i * 64) * SROW + ldq * 4) =
                make_float4(f2tf(ra[i].x), f2tf(ra[i].y), f2tf(ra[i].z), f2tf(ra[i].w));
        #pragma unroll
        for (int i = 0; i < 2; i++)
            *(float4*)(d + AF + (ldr + i * 64) * SROW + ldq * 4) =
                make_float4(f2tf(rb[i].x), f2tf(rb[i].y), f2tf(rb[i].z), f2tf(rb[i].w));
    };

    float acc[4][8][4];
    #pragma unroll
    for (int mt = 0; mt < 4; mt++)
        #pragma unroll
        for (int nt = 0; nt < 8; nt++)
            #pragma unroll
            for (int q = 0; q < 4; q++) acc[mt][nt][q] = 0.f;

    ldg(0);
    sts(0);
    if (KCz > 1) ldg(1);
    __syncthreads();

    for (int kt = 0; kt < KCz; kt++) {
        const uint32_t* As = (const uint32_t*)(sm + (kt & 1) * STAGE_F);
        const uint32_t* Bs = As + AF;
        #pragma unroll
        for (int kk = 0; kk < 2; kk++) {
            const int kb = kk * 8 + lc;
            uint32_t a[4][4], b[8][2];
            #pragma unroll
            for (int mt = 0; mt < 4; mt++) {
                const int r = wm * 64 + mt * 16 + lr;
                a[mt][0] = As[r * SROW + kb];
                a[mt][1] = As[(r + 8) * SROW + kb];
                a[mt][2] = As[r * SROW + kb + 4];
                a[mt][3] = As[(r + 8) * SROW + kb + 4];
            }
            #pragma unroll
            for (int nt = 0; nt < 8; nt++) {
                const int n = wn * 64 + nt * 8 + lr;
                b[nt][0] = Bs[n * SROW + kb];
                b[nt][1] = Bs[n * SROW + kb + 4];
            }
            #pragma unroll
            for (int mt = 0; mt < 4; mt++)
                #pragma unroll
                for (int nt = 0; nt < 8; nt++)
                    mma_tf32(acc[mt][nt], a[mt], b[nt]);
        }
        __syncthreads();
        if (kt + 1 < KCz) sts((kt + 1) & 1);
        if (kt + 2 < KCz) ldg(kt + 2);
        __syncthreads();
    }

    if (Z == 1) {
        #pragma unroll
        for (int mt = 0; mt < 4; mt++) {
            #pragma unroll
            for (int nt = 0; nt < 8; nt++) {
                const int row0 = m0 + wm * 64 + mt * 16 + lr;
                const int col  = n0 + wn * 64 + nt * 8 + 2 * lc;
                const float b0 = bias[col], b1 = bias[col + 1];
                float v0 = acc[mt][nt][0] + b0, v1 = acc[mt][nt][1] + b1;
                float v2 = acc[mt][nt][2] + b0, v3 = acc[mt][nt][3] + b1;
                if (ADDRES) {
                    float2 r0 = *(const float2*)(Res + (size_t)row0 * N + col);
                    float2 r1 = *(const float2*)(Res + (size_t)(row0 + 8) * N + col);
                    v0 += r0.x; v1 += r0.y; v2 += r1.x; v3 += r1.y;
                }
                if (RELU) {
                    v0 = fmaxf(v0, 0.f); v1 = fmaxf(v1, 0.f);
                    v2 = fmaxf(v2, 0.f); v3 = fmaxf(v3, 0.f);
                }
                *(float2*)(C + (size_t)row0 * N + col)       = make_float2(v0, v1);
                *(float2*)(C + (size_t)(row0 + 8) * N + col) = make_float2(v2, v3);
            }
        }
    } else {
        float* P = part + (size_t)blockIdx.z * M * N;
        #pragma unroll
        for (int mt = 0; mt < 4; mt++) {
            #pragma unroll
            for (int nt = 0; nt < 8; nt++) {
                const int row0 = m0 + wm * 64 + mt * 16 + lr;
                const int col  = n0 + wn * 64 + nt * 8 + 2 * lc;
                *(float2*)(P + (size_t)row0 * N + col)       = make_float2(acc[mt][nt][0], acc[mt][nt][1]);
                *(float2*)(P + (size_t)(row0 + 8) * N + col) = make_float2(acc[mt][nt][2], acc[mt][nt][3]);
            }
        }
    }
}

// ============================================================
// split-K merge: out = f( sum_z part[z] + bias (+res) ), optional relu
// ============================================================
template<bool RELU, bool ADDRES>
__global__ void __launch_bounds__(256) merge_k(
    const float* __restrict__ part, const float* __restrict__ bias,
    const float* __restrict__ Res, float* __restrict__ out,
    size_t MN, int N, int Z)
{
    const size_t i = ((size_t)blockIdx.x * 256 + threadIdx.x) * 4;
    float4 s = *(const float4*)(part + i);
    for (int z = 1; z < Z; z++) {
        float4 p = *(const float4*)(part + (size_t)z * MN + i);
        s.x += p.x; s.y += p.y; s.z += p.z; s.w += p.w;
    }
    const int col = (int)(i % (size_t)N);
    float4 bb = *(const float4*)(bias + col);
    s.x += bb.x; s.y += bb.y; s.z += bb.z; s.w += bb.w;
    if (ADDRES) {
        float4 rr = *(const float4*)(Res + i);
        s.x += rr.x; s.y += rr.y; s.z += rr.z; s.w += rr.w;
    }
    if (RELU) {
        s.x = fmaxf(s.x, 0.f); s.y = fmaxf(s.y, 0.f);
        s.z = fmaxf(s.z, 0.f); s.w = fmaxf(s.w, 0.f);
    }
    *(float4*)(out + i) = s;
}

// ============================================================
// LayerNorm over Dd per row
// ============================================================
__global__ void __launch_bounds__(256) ln_kernel(
    const float* __restrict__ in, const float* __restrict__ g,
    const float* __restrict__ b, float* __restrict__ out)
{
    const int row = blockIdx.x, t = threadIdx.x;
    const float4* p = (const float4*)(in + (size_t)row * Dd);
    float s = 0.f, s2 = 0.f;
    for (int i = t; i < Dd / 4; i += 256) {
        float4 v = p[i];
        s += v.x + v.y + v.z + v.w;
        s2 += v.x * v.x + v.y * v.y + v.z * v.z + v.w * v.w;
    }
    #pragma unroll
    for (int o = 16; o > 0; o >>= 1) {
        s  += __shfl_xor_sync(~0u, s, o);
        s2 += __shfl_xor_sync(~0u, s2, o);
    }
    __shared__ float rs[8], rs2[8], smean, sinv;
    if ((t & 31) == 0) { rs[t >> 5] = s; rs2[t >> 5] = s2; }
    __syncthreads();
    if (t == 0) {
        float ts = 0.f, ts2 = 0.f;
        #pragma unroll
        for (int i = 0; i < 8; i++) { ts += rs[i]; ts2 += rs2[i]; }
        float mean = ts * (1.f / Dd);
        smean = mean;
        sinv = rsqrtf(ts2 * (1.f / Dd) - mean * mean + 1e-5f);
    }
    __syncthreads();
    const float mean = smean, inv = sinv;
    const float4 *g4 = (const float4*)g, *b4 = (const float4*)b;
    float4* o4 = (float4*)(out + (size_t)row * Dd);
    for (int i = t; i < Dd / 4; i += 256) {
        float4 v = p[i], gg = g4[i], bb = b4[i], r;
        r.x = (v.x - mean) * inv * gg.x + bb.x;
        r.y = (v.y - mean) * inv * gg.y + bb.y;
        r.z = (v.z - mean) * inv * gg.z + bb.z;
        r.w = (v.w - mean) * inv * gg.w + bb.w;
        o4[i] = r;
    }
}

__global__ void __launch_bounds__(128) gap_kernel(
    const float* __restrict__ x, float* __restrict__ gap)
{
    const float* p = x + ((size_t)blockIdx.x * Cc + threadIdx.x) * 49;
    float a = 0.f;
    #pragma unroll
    for (int i = 0; i < 49; i++) a += p[i];
    gap[(size_t)blockIdx.x * Cc + threadIdx.x] = a * (1.f / 49.f);
}

// ============================================================
// Per-sample grouped dynamic 3x3 conv + residual
// ============================================================
__global__ void __launch_bounds__(128) dynconv_kernel(
    const float* __restrict__ x, const float* __restrict__ dyn,
    float* __restrict__ out)
{
    const int s = blockIdx.x, t = threadIdx.x;
    __shared__ float sIn[Cc][81];
    float* sc = sIn[t];
    #pragma unroll
    for (int i = 0; i < 81; i++) sc[i] = 0.f;
    const float* xp = x + ((size_t)s * Cc + t) * 49;
    #pragma unroll
    for (int y = 0; y < 7; y++)
        #pragma unroll
        for (int xx = 0; xx < 7; xx++)
            sc[(y + 1) * 9 + xx + 1] = xp[y * 7 + xx];
    __syncthreads();

    const int grp = t >> 5;
    const float* wb = dyn + (size_t)s * DYN + (size_t)t * (CPG * 9);
    const float* ib = &sIn[grp * CPG][0];
    float acc[49];
    #pragma unroll
    for (int i = 0; i < 49; i++) acc[i] = 0.f;
    for (int ic = 0; ic < CPG; ic++) {
        const float* w = wb + ic * 9;
        const float* in = ib + ic * 81;
        float w0 = w[0], w1 = w[1], w2 = w[2], w3 = w[3], w4 = w[4];
        float w5 = w[5], w6 = w[6], w7 = w[7], w8 = w[8];
        #pragma unroll
        for (int y = 0; y < 7; y++) {
            #pragma unroll
            for (int xx = 0; xx < 7; xx++) {
                float a = acc[y * 7 + xx];
                a += w0 * in[y * 9 + xx]       + w1 * in[y * 9 + xx + 1]       + w2 * in[y * 9 + xx + 2];
                a += w3 * in[(y + 1) * 9 + xx] + w4 * in[(y + 1) * 9 + xx + 1] + w5 * in[(y + 1) * 9 + xx + 2];
                a += w6 * in[(y + 2) * 9 + xx] + w7 * in[(y + 2) * 9 + xx + 1] + w8 * in[(y + 2) * 9 + xx + 2];
                acc[y * 7 + xx] = a;
            }
        }
    }
    float* op = out + ((size_t)s * Cc + t) * 49;
    const float* ms = sIn[t];
    #pragma unroll
    for (int y = 0; y < 7; y++)
        #pragma unroll
        for (int xx = 0; xx < 7; xx++)
            op[y * 7 + xx] = acc[y * 7 + xx] + ms[(y + 1) * 9 + xx + 1];
}

// ============================================================
// cost matrix
// ============================================================
__global__ void __launch_bounds__(256) cost_kernel(
    const float* __restrict__ rb, const float* __restrict__ cb, float* __restrict__ out)
{
    __shared__ float sR[Mb * 4], sC[Mb * 4], sdist[Mb * Mb], rm[8], sMax;
    const int t = threadIdx.x;
    sR[t] = rb[t]; sC[t] = cb[t];
    __syncthreads();
    float lm = 0.f;
    for (int idx = t; idx < Mb * Mb; idx += 256) {
        int i = idx >> 6, j = idx & 63;
        float d = fabsf((sR[i * 4] + sR[i * 4 + 2]) * 0.5f - (sC[j * 4] + sC[j * 4 + 2]) * 0.5f)
                + fabsf((sR[i * 4 + 1] + sR[i * 4 + 3]) * 0.5f - (sC[j * 4 + 1] + sC[j * 4 + 3]) * 0.5f);
        sdist[idx] = d;
        lm = fmaxf(lm, d);
    }
    #pragma unroll
    for (int o = 16; o > 0; o >>= 1) lm = fmaxf(lm, __shfl_xor_sync(~0u, lm, o));
    if ((t & 31) == 0) rm[t >> 5] = lm;
    __syncthreads();
    if (t == 0) {
        float m = 0.f;
        #pragma unroll
        for (int i = 0; i < 8; i++) m = fmaxf(m, rm[i]);
        sMax = fmaxf(m, 1.f);
    }
    __syncthreads();
    const float dmax = sMax;
    for (int idx = t; idx < Mb * Mb; idx += 256) {
        int i = idx >> 6, j = idx & 63;
        float ax0 = sR[i*4], ay0 = sR[i*4+1], ax1 = sR[i*4+2], ay1 = sR[i*4+3];
        float bx0 = sC[j*4], by0 = sC[j*4+1], bx1 = sC[j*4+2], by1 = sC[j*4+3];
        float areaA = (ax1 - ax0) * (ay1 - ay0), areaB = (bx1 - bx0) * (by1 - by0);
        float w = fmaxf(fminf(ax1, bx1) - fmaxf(ax0, bx0), 0.f);
        float h = fmaxf(fminf(ay1, by1) - fmaxf(ay0, by0), 0.f);
        float inter = w * h;
        out[idx] = -inter / (areaA + areaB - inter) + 0.5f * sdist[idx] / dmax;
    }
}

// ============================================================
// host launcher
// ============================================================
extern "C" void kernel_launch(void* const* d_in, const int* in_sizes, int n_in,
                              void* d_out, int out_size)
{
    const float* wf     = (const float*)d_in[0];
    const float* rf     = (const float*)d_in[1];
    const float* refb   = (const float*)d_in[2];
    const float* curb   = (const float*)d_in[3];
    // d_in[4..7] = wq,bq,wk,bk: dead (softmax over one key == 1 -> attn == v)
    const float* wv     = (const float*)d_in[8];
    const float* bv     = (const float*)d_in[9];
    const float* wo     = (const float*)d_in[10];
    const float* bo     = (const float*)d_in[11];
    const float* g1     = (const float*)d_in[12];
    const float* b1     = (const float*)d_in[13];
    const float* wgen_w = (const float*)d_in[14];
    const float* wgen_b = (const float*)d_in[15];
    const float* g2     = (const float*)d_in[16];
    const float* b2     = (const float*)d_in[17];
    const float* wf1    = (const float*)d_in[18];
    const float* bf1    = (const float*)d_in[19];
    const float* wf2    = (const float*)d_in[20];
    const float* bf2    = (const float*)d_in[21];
    const float* g3     = (const float*)d_in[22];
    const float* b3     = (const float*)d_in[23];
    float* out = (float*)d_out;

    float *v, *bufA, *x, *flat, *gap, *dyn, *h, *part;
    cudaGetSymbolAddress((void**)&v, g_v);       cudaGetSymbolAddress((void**)&bufA, g_bufA);
    cudaGetSymbolAddress((void**)&x, g_x);       cudaGetSymbolAddress((void**)&flat, g_flat);
    cudaGetSymbolAddress((void**)&gap, g_gap);   cudaGetSymbolAddress((void**)&dyn, g_dyn);
    cudaGetSymbolAddress((void**)&h, g_h);       cudaGetSymbolAddress((void**)&part, g_part);

    cudaFuncSetAttribute(gemm_f<false, false>, cudaFuncAttributeMaxDynamicSharedMemorySize, GEMM_SMEM);
    cudaFuncSetAttribute(gemm_f<false, true>,  cudaFuncAttributeMaxDynamicSharedMemorySize, GEMM_SMEM);

    const size_t MN1 = (size_t)Kn * Dd;     // 6.42M
    const size_t MNF = (size_t)Kn * FFNn;   // 1.05M

    // 1. v = rf @ wv^T + bv              (split-K2)
    gemm_f<false, false><<<dim3(4, 49, 2), 256, GEMM_SMEM>>>(rf, wv, bv, nullptr, v, part, Dd, Dd, 392);
    merge_k<false, false><<<(int)(MN1 / 1024), 256>>>(part, bv, nullptr, v, MN1, Dd, 2);
    // 2. bufA = v @ wo^T + bo + wf       (split-K2)
    gemm_f<false, false><<<dim3(4, 49, 2), 256, GEMM_SMEM>>>(v, wo, bo, nullptr, bufA, part, Dd, Dd, 392);
    merge_k<false, true><<<(int)(MN1 / 1024), 256>>>(part, bo, wf, bufA, MN1, Dd, 2);
    // 3. x = LN(bufA)
    ln_kernel<<<Kn, 256>>>(bufA, g1, b1, x);
    // 4. gap
    gap_kernel<<<Kn, 128>>>(x, gap);
    // 5. dyn = gap @ wgen^T + wgen_b     (Z=1, 1152 CTAs)
    gemm_f<false, false><<<dim3(4, 288, 1), 256, GEMM_SMEM>>>(gap, wgen_w, wgen_b, nullptr, dyn, part, DYN, Cc, 8);
    // 6. bufA = dynconv(x) + x
    dynconv_kernel<<<Kn, 128>>>(x, dyn, bufA);
    // 7. flat = LN(bufA)
    ln_kernel<<<Kn, 256>>>(bufA, g2, b2, flat);
    // 8. h = relu(flat @ wf1^T + bf1)    (split-K4)
    gemm_f<false, false><<<dim3(4, 8, 4), 256, GEMM_SMEM>>>(flat, wf1, bf1, nullptr, h, part, FFNn, Dd, 392);
    merge_k<true, false><<<(int)(MNF / 1024), 256>>>(part, bf1, nullptr, h, MNF, FFNn, 4);
    // 9. bufA = h @ wf2^T + bf2 + flat   (Z=1 direct)
    gemm_f<false, true><<<dim3(4, 49, 1), 256, GEMM_SMEM>>>(h, wf2, bf2, flat, bufA, part, Dd, FFNn, 64);
    // 10. out = LN(bufA)
    ln_kernel<<<Kn, 256>>>(bufA, g3, b3, out);
    // 11. cost matrix
    cost_kernel<<<1, 256>>>(refb, curb, out + (size_t)Kn * Dd);
}